// round 11
// baseline (speedup 1.0000x reference)
#include <cuda_runtime.h>
#include <cuda_fp16.h>
#include <cstddef>

#define NN 100000
#define EE 1600000
#define GG 512
#define DD 64

// ---------------- scratch (static __device__, no allocation) ----------------
__device__ __align__(256) float  g_h[(size_t)NN * DD];
__device__ __align__(256) __half g_a[(size_t)NN * DD];   // fp16 rows: 128B each
__device__ __align__(256) float  g_z[(size_t)NN * DD];
__device__ __align__(256) float  g_degw[NN];
__device__ __align__(256) float  g_psum[GG * DD];
__device__ __align__(256) float  g_pcnt[GG];
__device__ __align__(256) int    g_cnt[NN];
__device__ __align__(256) int    g_rowstart[NN];
__device__ __align__(256) int    g_cursor[NN];
__device__ __align__(256) int2   g_epack[EE];     // (src, w bits), grouped by dst
__device__ __align__(256) int    g_bsum[512];
__device__ __align__(256) int    g_boff[512];
__device__ __align__(256) int    g_batch[NN];
__device__ int   g_eflag;   // nonzero -> edge_index stored as int32
__device__ int   g_bflag;   // nonzero -> batch stored as int32

// ---------------- dtype detection ----------------
__global__ void detect_kernel(const int* __restrict__ ei32,
                              const int* __restrict__ b32,
                              int* __restrict__ eflag, int* __restrict__ bflag) {
    __shared__ int se, sb;
    if (threadIdx.x == 0) { se = 0; sb = 0; }
    __syncthreads();
    int e = 0, b = 0;
    for (int i = threadIdx.x; i < 1024; i += blockDim.x) {
        e |= ei32[2 * i + 1];
        b |= b32[NN / 2 + 2 * i + 1];
    }
    if (e) atomicOr(&se, 1);
    if (b) atomicOr(&sb, 1);
    __syncthreads();
    if (threadIdx.x == 0) { *eflag = se; *bflag = sb; }
}

__global__ void cvt_batch_kernel(const int* __restrict__ b32,
                                 int* __restrict__ batch,
                                 const int* __restrict__ bflag) {
    int n = blockIdx.x * blockDim.x + threadIdx.x;
    if (n >= NN) return;
    batch[n] = (*bflag) ? b32[n] : b32[2 * n];
}

// ---------------- CSR build: histogram of dst ----------------
__global__ void hist_kernel(const int* __restrict__ ei32,
                            int* __restrict__ cnt,
                            const int* __restrict__ eflag) {
    int e = blockIdx.x * blockDim.x + threadIdx.x;
    if (e >= EE) return;
    int d = (*eflag) ? ei32[EE + e] : ei32[2 * ((size_t)EE + e)];
    atomicAdd(&cnt[d], 1);
}

// ---------------- 3-kernel prefix scan over cnt -> rowstart ----------------
__global__ void scan1_kernel(const int* __restrict__ cnt,
                             int* __restrict__ rowstart, int* __restrict__ bsum) {
    int i = blockIdx.x * 256 + threadIdx.x;
    int v = (i < NN) ? cnt[i] : 0;
    int lane = threadIdx.x & 31, wid = threadIdx.x >> 5;
    int x = v;
    #pragma unroll
    for (int o = 1; o < 32; o <<= 1) {
        int y = __shfl_up_sync(~0u, x, o);
        if (lane >= o) x += y;
    }
    __shared__ int ws[8];
    if (lane == 31) ws[wid] = x;
    __syncthreads();
    if (wid == 0) {
        int y = (lane < 8) ? ws[lane] : 0;
        #pragma unroll
        for (int o = 1; o < 8; o <<= 1) {
            int z = __shfl_up_sync(~0u, y, o);
            if (lane >= o) y += z;
        }
        if (lane < 8) ws[lane] = y;
    }
    __syncthreads();
    int incl = x + (wid > 0 ? ws[wid - 1] : 0);
    if (i < NN) rowstart[i] = incl - v;
    if (threadIdx.x == 255) bsum[blockIdx.x] = incl;
}

__global__ void scan2_kernel(const int* __restrict__ bsum, int* __restrict__ boff,
                             int nblocks) {
    int i = threadIdx.x;  // 512 threads
    int v = (i < nblocks) ? bsum[i] : 0;
    int lane = i & 31, wid = i >> 5;
    int x = v;
    #pragma unroll
    for (int o = 1; o < 32; o <<= 1) {
        int y = __shfl_up_sync(~0u, x, o);
        if (lane >= o) x += y;
    }
    __shared__ int ws[16];
    if (lane == 31) ws[wid] = x;
    __syncthreads();
    if (wid == 0) {
        int y = (lane < 16) ? ws[lane] : 0;
        #pragma unroll
        for (int o = 1; o < 16; o <<= 1) {
            int z = __shfl_up_sync(~0u, y, o);
            if (lane >= o) y += z;
        }
        if (lane < 16) ws[lane] = y;
    }
    __syncthreads();
    int incl = x + (wid > 0 ? ws[wid - 1] : 0);
    if (i < nblocks) boff[i] = incl - v;
}

__global__ void scan3_kernel(int* __restrict__ rowstart, int* __restrict__ cursor,
                             const int* __restrict__ boff) {
    int i = blockIdx.x * 256 + threadIdx.x;
    if (i >= NN) return;
    int r = rowstart[i] + boff[blockIdx.x];
    rowstart[i] = r;
    cursor[i] = r;
}

// ---------------- CSR fill: epack[pos] = (src, w) grouped by dst ----------------
__global__ void fill_kernel(const int* __restrict__ ei32,
                            const float* __restrict__ ea,
                            int* __restrict__ cursor,
                            int2* __restrict__ epack,
                            const int* __restrict__ eflag) {
    int e = blockIdx.x * blockDim.x + threadIdx.x;
    if (e >= EE) return;
    int s, d;
    if (*eflag) {
        s = ei32[e];
        d = ei32[EE + e];
    } else {
        s = ei32[2 * (size_t)e];
        d = ei32[2 * ((size_t)EE + e)];
    }
    int pos = atomicAdd(&cursor[d], 1);
    epack[pos] = make_int2(s, __float_as_int(ea[e]));
}

// ---------------- deg_w from CSR (no atomics) ----------------
__global__ void degw_kernel(const int* __restrict__ rowstart,
                            const int* __restrict__ cnt,
                            const int2* __restrict__ epack,
                            float* __restrict__ degw) {
    int n = blockIdx.x * blockDim.x + threadIdx.x;
    if (n >= NN) return;
    int s = rowstart[n], c = cnt[n];
    float sum = 0.f;
    for (int j = 0; j < c; j++) sum += __int_as_float(epack[s + j].y);
    degw[n] = sum;
}

// ---------------- h = x @ W_emb + b_emb ----------------
__global__ void embed_kernel(const float* __restrict__ x,
                             const float* __restrict__ Wemb,
                             const float* __restrict__ bemb,
                             float* __restrict__ h) {
    int t = blockIdx.x * blockDim.x + threadIdx.x;
    if (t >= NN * 16) return;
    int n = t >> 4;
    int q = t & 15;
    float4 xv = ((const float4*)x)[n];
    const float4* W4 = (const float4*)Wemb;
    float4 w0 = W4[0 * 16 + q];
    float4 w1 = W4[1 * 16 + q];
    float4 w2 = W4[2 * 16 + q];
    float4 w3 = W4[3 * 16 + q];
    float4 bb = ((const float4*)bemb)[q];
    float4 o;
    o.x = bb.x + xv.x * w0.x + xv.y * w1.x + xv.z * w2.x + xv.w * w3.x;
    o.y = bb.y + xv.x * w0.y + xv.y * w1.y + xv.z * w2.y + xv.w * w3.y;
    o.z = bb.z + xv.x * w0.z + xv.y * w1.z + xv.z * w2.z + xv.w * w3.z;
    o.w = bb.w + xv.x * w0.w + xv.y * w1.w + xv.z * w2.w + xv.w * w3.w;
    ((float4*)h)[(size_t)n * 16 + q] = o;
}

// ---------------- fused per-layer GEMMs (f32x2 packed) ----------------
// a = fp16(h@W1 + b1) ; z = h@W3 + b3 - deg_w ⊙ (h@W2)  (z stored evict-first)
__global__ __launch_bounds__(512) void gemm3_kernel(
    const float* __restrict__ h,
    const float* __restrict__ W1, const float* __restrict__ b1,
    const float* __restrict__ W2,
    const float* __restrict__ W3, const float* __restrict__ b3,
    const float* __restrict__ degw,
    __half* __restrict__ a_out, float* __restrict__ z_out) {
    __shared__ __align__(16) float hT[64][128];
    __shared__ __align__(16) float sW[64][64];
    const int tid = threadIdx.x;
    const int nodeBase = blockIdx.x * 128;

    {
        const int n = tid & 127;
        const int kq = tid >> 7;
        const int gn = nodeBase + n;
        #pragma unroll
        for (int kk = 0; kk < 4; kk++) {
            const int k4 = kq * 16 + kk * 4;
            float4 v = make_float4(0.f, 0.f, 0.f, 0.f);
            if (gn < NN) v = *(const float4*)(h + (size_t)gn * 64 + k4);
            hT[k4 + 0][n] = v.x;
            hT[k4 + 1][n] = v.y;
            hT[k4 + 2][n] = v.z;
            hT[k4 + 3][n] = v.w;
        }
    }

    const int tx = tid & 63;
    const int ty = tid >> 6;
    const int nb = ty * 16;

    unsigned long long bacc[8];

    #pragma unroll 1
    for (int m = 0; m < 3; m++) {
        const float* Wm = (m == 0) ? W1 : (m == 1) ? W2 : W3;
        __syncthreads();
        #pragma unroll
        for (int i = 0; i < 2; i++)
            ((float4*)sW)[tid + i * 512] = ((const float4*)Wm)[tid + i * 512];
        __syncthreads();

        unsigned long long acc[8];
        #pragma unroll
        for (int p = 0; p < 8; p++) acc[p] = 0ULL;

        #pragma unroll 8
        for (int k = 0; k < 64; k++) {
            float w = sW[k][tx];
            unsigned long long ws;
            asm("mov.b64 %0, {%1, %1};" : "=l"(ws) : "f"(w));
            #pragma unroll
            for (int i = 0; i < 4; i++) {
                ulonglong2 hv = *(const ulonglong2*)&hT[k][nb + 4 * i];
                asm("fma.rn.f32x2 %0, %1, %2, %0;" : "+l"(acc[2 * i])     : "l"(ws), "l"(hv.x));
                asm("fma.rn.f32x2 %0, %1, %2, %0;" : "+l"(acc[2 * i + 1]) : "l"(ws), "l"(hv.y));
            }
        }

        if (m == 0) {
            const float bias = b1[tx];
            #pragma unroll
            for (int p = 0; p < 8; p++) {
                float f0, f1;
                asm("mov.b64 {%0, %1}, %2;" : "=f"(f0), "=f"(f1) : "l"(acc[p]));
                const int n = nodeBase + nb + 2 * p;
                if (n < NN)     a_out[(size_t)n * 64 + tx]       = __float2half(f0 + bias);
                if (n + 1 < NN) a_out[(size_t)(n + 1) * 64 + tx] = __float2half(f1 + bias);
            }
        } else if (m == 1) {
            #pragma unroll
            for (int p = 0; p < 8; p++) bacc[p] = acc[p];
        } else {
            const float bias = b3[tx];
            #pragma unroll
            for (int p = 0; p < 8; p++) {
                float f0, f1, g0, g1;
                asm("mov.b64 {%0, %1}, %2;" : "=f"(f0), "=f"(f1) : "l"(acc[p]));
                asm("mov.b64 {%0, %1}, %2;" : "=f"(g0), "=f"(g1) : "l"(bacc[p]));
                const int n = nodeBase + nb + 2 * p;
                if (n < NN) {
                    float dw = degw[n];
                    __stcs(&z_out[(size_t)n * 64 + tx], f0 + bias - dw * g0);
                }
                if (n + 1 < NN) {
                    float dw = degw[n + 1];
                    __stcs(&z_out[(size_t)(n + 1) * 64 + tx], f1 + bias - dw * g1);
                }
            }
        }
    }
}

// ---------------- gather: h[n] = relu(z[n] + sum_{e->n} w_e * fp32(a[src_e])) --------
// 8 lanes/node. Cooperative edge fetch: one LDG brings 8 edge records into the
// 8-lane group; shfl broadcasts each record; the 8 row loads issue back-to-back
// (no epack->row serial chain). Next group's epack load is software-pipelined.
__global__ __launch_bounds__(256) void gather_kernel(
                              const int* __restrict__ rowstart,
                              const int* __restrict__ cnt,
                              const int2* __restrict__ epack,
                              const __half* __restrict__ a,
                              const float* __restrict__ z,
                              float* __restrict__ h,
                              const int* __restrict__ batch,
                              float* __restrict__ psum,
                              float* __restrict__ pcnt,
                              int do_pool) {
    int t = blockIdx.x * blockDim.x + threadIdx.x;
    int n = t >> 3;
    if (n >= NN) return;
    int lane = t & 7;          // 8 floats each (dims lane*8 .. lane*8+7)
    unsigned gmask = 0xFFu << (((unsigned)threadIdx.x & 24u));  // 8-lane group mask
    int s = __ldg(rowstart + n);
    int c = __ldg(cnt + n);
    const uint4* a4 = (const uint4*)a;   // 8 halves per uint4; 8 uint4 per row

    const float4* zp4 = (const float4*)z + (size_t)n * 16 + lane * 2;
    float4 acc0 = __ldcs(zp4);
    float4 acc1 = __ldcs(zp4 + 1);

    #define ACC_EDGE(V, W) do {                                              \
        const __half2* hv_ = (const __half2*)&(V);                           \
        float2 f0_ = __half22float2(hv_[0]);                                 \
        float2 f1_ = __half22float2(hv_[1]);                                 \
        float2 f2_ = __half22float2(hv_[2]);                                 \
        float2 f3_ = __half22float2(hv_[3]);                                 \
        acc0.x = fmaf((W), f0_.x, acc0.x); acc0.y = fmaf((W), f0_.y, acc0.y);\
        acc0.z = fmaf((W), f1_.x, acc0.z); acc0.w = fmaf((W), f1_.y, acc0.w);\
        acc1.x = fmaf((W), f2_.x, acc1.x); acc1.y = fmaf((W), f2_.y, acc1.y);\
        acc1.z = fmaf((W), f3_.x, acc1.z); acc1.w = fmaf((W), f3_.y, acc1.w);\
    } while (0)

    int j = 0;
    if (c >= 8) {
        int2 p = __ldg(epack + s + lane);      // 8 edge records, one per lane
        for (; j + 8 <= c; j += 8) {
            int2 pn = p;
            if (j + 16 <= c) pn = __ldg(epack + s + j + 8 + lane);  // pipeline next
            #pragma unroll
            for (int k = 0; k < 8; k++) {
                int   sk = __shfl_sync(gmask, p.x, k, 8);
                float wk = __int_as_float(__shfl_sync(gmask, p.y, k, 8));
                uint4 v = __ldg(a4 + (size_t)sk * 8 + lane);
                ACC_EDGE(v, wk);
            }
            p = pn;
        }
    }
    if (j < c) {                               // tail: 1..7 edges
        int rem = c - j;
        int idx = j + lane;
        if (idx >= c) idx = c - 1;
        int2 p = __ldg(epack + s + idx);
        #pragma unroll
        for (int k = 0; k < 8; k++) {
            if (k < rem) {
                int   sk = __shfl_sync(gmask, p.x, k, 8);
                float wk = __int_as_float(__shfl_sync(gmask, p.y, k, 8));
                uint4 v = __ldg(a4 + (size_t)sk * 8 + lane);
                ACC_EDGE(v, wk);
            }
        }
    }
    #undef ACC_EDGE

    acc0.x = fmaxf(acc0.x, 0.f); acc0.y = fmaxf(acc0.y, 0.f);
    acc0.z = fmaxf(acc0.z, 0.f); acc0.w = fmaxf(acc0.w, 0.f);
    acc1.x = fmaxf(acc1.x, 0.f); acc1.y = fmaxf(acc1.y, 0.f);
    acc1.z = fmaxf(acc1.z, 0.f); acc1.w = fmaxf(acc1.w, 0.f);
    float4* hp4 = (float4*)h + (size_t)n * 16 + lane * 2;
    hp4[0] = acc0;
    hp4[1] = acc1;

    if (do_pool) {
        int g = __ldg(batch + n);
        float* p = psum + (size_t)g * 64 + lane * 8;
        asm volatile("red.global.add.v4.f32 [%0], {%1, %2, %3, %4};"
                     :: "l"(p), "f"(acc0.x), "f"(acc0.y), "f"(acc0.z), "f"(acc0.w) : "memory");
        asm volatile("red.global.add.v4.f32 [%0], {%1, %2, %3, %4};"
                     :: "l"(p + 4), "f"(acc1.x), "f"(acc1.y), "f"(acc1.z), "f"(acc1.w) : "memory");
        if (lane == 0)
            asm volatile("red.global.add.f32 [%0], %1;" :: "l"(pcnt + g), "f"(1.0f) : "memory");
    }
}

// ---------------- final MLP head ----------------
__global__ void mlp_kernel(const float* __restrict__ psum,
                           const float* __restrict__ pcnt,
                           const float* __restrict__ Wl1, const float* __restrict__ bl1,
                           const float* __restrict__ Wl2, const float* __restrict__ bl2,
                           float* __restrict__ out) {
    __shared__ float sW1[64 * 32];
    __shared__ float sW2[32 * 3];
    __shared__ float sb1[32];
    __shared__ float sb2[3];
    int tid = threadIdx.x;
    for (int i = tid; i < 64 * 32; i += blockDim.x) sW1[i] = Wl1[i];
    for (int i = tid; i < 32 * 3; i += blockDim.x) sW2[i] = Wl2[i];
    if (tid < 32) sb1[tid] = bl1[tid];
    if (tid < 3) sb2[tid] = bl2[tid];
    __syncthreads();

    int g = blockIdx.x * blockDim.x + tid;
    if (g >= GG) return;
    float inv = 1.0f / fmaxf(pcnt[g], 1.0f);
    float hid[32];
    #pragma unroll
    for (int j = 0; j < 32; j++) hid[j] = sb1[j];
    #pragma unroll 8
    for (int k = 0; k < 64; k++) {
        float xv = psum[(size_t)g * 64 + k] * inv;
        #pragma unroll
        for (int j = 0; j < 32; j++) hid[j] += xv * sW1[k * 32 + j];
    }
    #pragma unroll
    for (int j = 0; j < 32; j++) hid[j] = fmaxf(hid[j], 0.f);
    #pragma unroll
    for (int c = 0; c < 3; c++) {
        float o = sb2[c];
        #pragma unroll
        for (int j = 0; j < 32; j++) o += hid[j] * sW2[j * 3 + c];
        out[g * 3 + c] = o;
    }
}

// ---------------- launch ----------------
extern "C" void kernel_launch(void* const* d_in, const int* in_sizes, int n_in,
                              void* d_out, int out_size) {
    const float* x        = (const float*)d_in[0];
    const int*   ei32     = (const int*)d_in[1];
    const float* ea       = (const float*)d_in[2];
    const int*   b32      = (const int*)d_in[3];
    const float* Wemb     = (const float*)d_in[4];
    const float* bemb     = (const float*)d_in[5];
    const float* W1       = (const float*)d_in[6];
    const float* b1       = (const float*)d_in[7];
    const float* W2       = (const float*)d_in[8];
    const float* W3       = (const float*)d_in[9];
    const float* b3       = (const float*)d_in[10];
    const float* Wl1      = (const float*)d_in[11];
    const float* bl1      = (const float*)d_in[12];
    const float* Wl2      = (const float*)d_in[13];
    const float* bl2      = (const float*)d_in[14];
    float* out = (float*)d_out;

    float *hp, *zp, *dwp, *psp, *pcp;
    __half* ap;
    int *cntp, *rsp, *curp, *bsp, *bop, *bp, *efp, *bfp;
    int2* epp;
    cudaGetSymbolAddress((void**)&hp, g_h);
    cudaGetSymbolAddress((void**)&ap, g_a);
    cudaGetSymbolAddress((void**)&zp, g_z);
    cudaGetSymbolAddress((void**)&dwp, g_degw);
    cudaGetSymbolAddress((void**)&psp, g_psum);
    cudaGetSymbolAddress((void**)&pcp, g_pcnt);
    cudaGetSymbolAddress((void**)&cntp, g_cnt);
    cudaGetSymbolAddress((void**)&rsp, g_rowstart);
    cudaGetSymbolAddress((void**)&curp, g_cursor);
    cudaGetSymbolAddress((void**)&bsp, g_bsum);
    cudaGetSymbolAddress((void**)&bop, g_boff);
    cudaGetSymbolAddress((void**)&epp, g_epack);
    cudaGetSymbolAddress((void**)&bp, g_batch);
    cudaGetSymbolAddress((void**)&efp, g_eflag);
    cudaGetSymbolAddress((void**)&bfp, g_bflag);

    cudaMemsetAsync(cntp, 0, NN * sizeof(int));
    cudaMemsetAsync(psp, 0, GG * DD * sizeof(float));
    cudaMemsetAsync(pcp, 0, GG * sizeof(float));

    const int scanBlocks = (NN + 255) / 256;   // 391

    detect_kernel<<<1, 256>>>(ei32, b32, efp, bfp);
    cvt_batch_kernel<<<(NN + 255) / 256, 256>>>(b32, bp, bfp);
    hist_kernel<<<(EE + 255) / 256, 256>>>(ei32, cntp, efp);
    scan1_kernel<<<scanBlocks, 256>>>(cntp, rsp, bsp);
    scan2_kernel<<<1, 512>>>(bsp, bop, scanBlocks);
    scan3_kernel<<<scanBlocks, 256>>>(rsp, curp, bop);
    fill_kernel<<<(EE + 255) / 256, 256>>>(ei32, ea, curp, epp, efp);
    degw_kernel<<<(NN + 255) / 256, 256>>>(rsp, cntp, epp, dwp);

    embed_kernel<<<(NN * 16 + 255) / 256, 256>>>(x, Wemb, bemb, hp);

    const int gemmBlocks = (NN + 127) / 128;
    const int gatherBlocks = (NN * 8 + 255) / 256;

    for (int l = 0; l < 3; l++) {
        gemm3_kernel<<<gemmBlocks, 512>>>(hp,
                                          W1 + (size_t)l * DD * DD, b1 + (size_t)l * DD,
                                          W2 + (size_t)l * DD * DD,
                                          W3 + (size_t)l * DD * DD, b3 + (size_t)l * DD,
                                          dwp, ap, zp);
        gather_kernel<<<gatherBlocks, 256>>>(rsp, cntp, epp, ap, zp, hp,
                                             bp, psp, pcp, (l == 2) ? 1 : 0);
    }

    mlp_kernel<<<2, 256>>>(psp, pcp, Wl1, bl1, Wl2, bl2, out);
}

// round 13
// speedup vs baseline: 1.9277x; 1.9277x over previous
#include <cuda_runtime.h>
#include <cuda_fp16.h>
#include <cstddef>
#include <cstdint>

#define NN 100000
#define EE 1600000
#define GG 512
#define DD 64

// ---------------- scratch (static __device__, no allocation) ----------------
__device__ __align__(256) float  g_h[(size_t)NN * DD];
__device__ __align__(256) __half g_a[(size_t)NN * DD];   // fp16 rows: 128B each
__device__ __align__(256) float  g_z[(size_t)NN * DD];
__device__ __align__(256) float  g_degw[NN];
__device__ __align__(256) float  g_psum[GG * DD];
__device__ __align__(256) float  g_pcnt[GG];
__device__ __align__(256) int    g_cnt[NN];
__device__ __align__(256) int    g_rowstart[NN];
__device__ __align__(256) int    g_cursor[NN];
__device__ __align__(256) int2   g_epack[EE];     // (src, w bits), grouped by dst
__device__ __align__(256) int    g_bsum[512];
__device__ __align__(256) int    g_boff[512];
__device__ __align__(256) int    g_batch[NN];
__device__ __align__(256) __half g_wt[9 * 4096];  // [l][m][o][k] = W_m[l][k][o] fp16
__device__ int   g_eflag;   // nonzero -> edge_index stored as int32
__device__ int   g_bflag;   // nonzero -> batch stored as int32

__device__ __forceinline__ uint32_t smem_u32(const void* p) {
    uint32_t a;
    asm("{ .reg .u64 t; cvta.to.shared.u64 t, %1; cvt.u32.u64 %0, t; }" : "=r"(a) : "l"(p));
    return a;
}

// ---------------- dtype detection ----------------
__global__ void detect_kernel(const int* __restrict__ ei32,
                              const int* __restrict__ b32,
                              int* __restrict__ eflag, int* __restrict__ bflag) {
    __shared__ int se, sb;
    if (threadIdx.x == 0) { se = 0; sb = 0; }
    __syncthreads();
    int e = 0, b = 0;
    for (int i = threadIdx.x; i < 1024; i += blockDim.x) {
        e |= ei32[2 * i + 1];
        b |= b32[NN / 2 + 2 * i + 1];
    }
    if (e) atomicOr(&se, 1);
    if (b) atomicOr(&sb, 1);
    __syncthreads();
    if (threadIdx.x == 0) { *eflag = se; *bflag = sb; }
}

__global__ void cvt_batch_kernel(const int* __restrict__ b32,
                                 int* __restrict__ batch,
                                 const int* __restrict__ bflag) {
    int n = blockIdx.x * blockDim.x + threadIdx.x;
    if (n >= NN) return;
    batch[n] = (*bflag) ? b32[n] : b32[2 * n];
}

// ---------------- CSR build: histogram of dst ----------------
__global__ void hist_kernel(const int* __restrict__ ei32,
                            int* __restrict__ cnt,
                            const int* __restrict__ eflag) {
    int e = blockIdx.x * blockDim.x + threadIdx.x;
    if (e >= EE) return;
    int d = (*eflag) ? ei32[EE + e] : ei32[2 * ((size_t)EE + e)];
    atomicAdd(&cnt[d], 1);
}

// ---------------- 3-kernel prefix scan over cnt -> rowstart ----------------
__global__ void scan1_kernel(const int* __restrict__ cnt,
                             int* __restrict__ rowstart, int* __restrict__ bsum) {
    int i = blockIdx.x * 256 + threadIdx.x;
    int v = (i < NN) ? cnt[i] : 0;
    int lane = threadIdx.x & 31, wid = threadIdx.x >> 5;
    int x = v;
    #pragma unroll
    for (int o = 1; o < 32; o <<= 1) {
        int y = __shfl_up_sync(~0u, x, o);
        if (lane >= o) x += y;
    }
    __shared__ int ws[8];
    if (lane == 31) ws[wid] = x;
    __syncthreads();
    if (wid == 0) {
        int y = (lane < 8) ? ws[lane] : 0;
        #pragma unroll
        for (int o = 1; o < 8; o <<= 1) {
            int z = __shfl_up_sync(~0u, y, o);
            if (lane >= o) y += z;
        }
        if (lane < 8) ws[lane] = y;
    }
    __syncthreads();
    int incl = x + (wid > 0 ? ws[wid - 1] : 0);
    if (i < NN) rowstart[i] = incl - v;
    if (threadIdx.x == 255) bsum[blockIdx.x] = incl;
}

__global__ void scan2_kernel(const int* __restrict__ bsum, int* __restrict__ boff,
                             int nblocks) {
    int i = threadIdx.x;  // 512 threads
    int v = (i < nblocks) ? bsum[i] : 0;
    int lane = i & 31, wid = i >> 5;
    int x = v;
    #pragma unroll
    for (int o = 1; o < 32; o <<= 1) {
        int y = __shfl_up_sync(~0u, x, o);
        if (lane >= o) x += y;
    }
    __shared__ int ws[16];
    if (lane == 31) ws[wid] = x;
    __syncthreads();
    if (wid == 0) {
        int y = (lane < 16) ? ws[lane] : 0;
        #pragma unroll
        for (int o = 1; o < 16; o <<= 1) {
            int z = __shfl_up_sync(~0u, y, o);
            if (lane >= o) y += z;
        }
        if (lane < 16) ws[lane] = y;
    }
    __syncthreads();
    int incl = x + (wid > 0 ? ws[wid - 1] : 0);
    if (i < nblocks) boff[i] = incl - v;
}

__global__ void scan3_kernel(int* __restrict__ rowstart, int* __restrict__ cursor,
                             const int* __restrict__ boff) {
    int i = blockIdx.x * 256 + threadIdx.x;
    if (i >= NN) return;
    int r = rowstart[i] + boff[blockIdx.x];
    rowstart[i] = r;
    cursor[i] = r;
}

// ---------------- CSR fill: epack[pos] = (src, w) grouped by dst ----------------
__global__ void fill_kernel(const int* __restrict__ ei32,
                            const float* __restrict__ ea,
                            int* __restrict__ cursor,
                            int2* __restrict__ epack,
                            const int* __restrict__ eflag) {
    int e = blockIdx.x * blockDim.x + threadIdx.x;
    if (e >= EE) return;
    int s, d;
    if (*eflag) {
        s = ei32[e];
        d = ei32[EE + e];
    } else {
        s = ei32[2 * (size_t)e];
        d = ei32[2 * ((size_t)EE + e)];
    }
    int pos = atomicAdd(&cursor[d], 1);
    epack[pos] = make_int2(s, __float_as_int(ea[e]));
}

// ---------------- deg_w from CSR (no atomics) ----------------
__global__ void degw_kernel(const int* __restrict__ rowstart,
                            const int* __restrict__ cnt,
                            const int2* __restrict__ epack,
                            float* __restrict__ degw) {
    int n = blockIdx.x * blockDim.x + threadIdx.x;
    if (n >= NN) return;
    int s = rowstart[n], c = cnt[n];
    float sum = 0.f;
    for (int j = 0; j < c; j++) sum += __int_as_float(epack[s + j].y);
    degw[n] = sum;
}

// ---------------- WT prep: wt[l][m][o][k] = fp16(W_m[l][k][o]) ----------------
__global__ void prep_wt_kernel(const float* __restrict__ W1,
                               const float* __restrict__ W2,
                               const float* __restrict__ W3,
                               __half* __restrict__ wt) {
    int t = blockIdx.x * blockDim.x + threadIdx.x;
    if (t >= 9 * 4096) return;
    int l = t / 12288;
    int rem = t % 12288;
    int m = rem / 4096;
    int e = rem % 4096;
    int o = e >> 6, k = e & 63;
    const float* W = (m == 0) ? W1 : (m == 1) ? W2 : W3;
    wt[t] = __float2half(W[(size_t)l * 4096 + k * 64 + o]);
}

// ---------------- h = x @ W_emb + b_emb ----------------
__global__ void embed_kernel(const float* __restrict__ x,
                             const float* __restrict__ Wemb,
                             const float* __restrict__ bemb,
                             float* __restrict__ h) {
    int t = blockIdx.x * blockDim.x + threadIdx.x;
    if (t >= NN * 16) return;
    int n = t >> 4;
    int q = t & 15;
    float4 xv = ((const float4*)x)[n];
    const float4* W4 = (const float4*)Wemb;
    float4 w0 = W4[0 * 16 + q];
    float4 w1 = W4[1 * 16 + q];
    float4 w2 = W4[2 * 16 + q];
    float4 w3 = W4[3 * 16 + q];
    float4 bb = ((const float4*)bemb)[q];
    float4 o;
    o.x = bb.x + xv.x * w0.x + xv.y * w1.x + xv.z * w2.x + xv.w * w3.x;
    o.y = bb.y + xv.x * w0.y + xv.y * w1.y + xv.z * w2.y + xv.w * w3.y;
    o.z = bb.z + xv.x * w0.z + xv.y * w1.z + xv.z * w2.z + xv.w * w3.z;
    o.w = bb.w + xv.x * w0.w + xv.y * w1.w + xv.z * w2.w + xv.w * w3.w;
    ((float4*)h)[(size_t)n * 16 + q] = o;
}

// ---------------- HMMA fused per-layer GEMMs (mma.sync m16n8k16) ----------------
// D1 = A·W1^T -> a = fp16(D1+b1); D2 = A·W2^T; D3 = A·W3^T;
// z = D3 + b3 - deg_w ⊙ D2.  256-node tile, 512 threads (16 warps × m16).
#define GSTR 144   // smem row stride in bytes (72 halves) — conflict-free ldmatrix

__global__ __launch_bounds__(512) void gemm3_mma_kernel(
    const float* __restrict__ h,
    const __half* __restrict__ wt,    // this layer: [3][64][64] (o-major = B^T)
    const float* __restrict__ b1, const float* __restrict__ b3,
    const float* __restrict__ degw,
    __half* __restrict__ a_out, float* __restrict__ z_out) {
    __shared__ __align__(16) unsigned char sA[256 * GSTR];   // 36864 B
    __shared__ __align__(16) unsigned char sB[64 * GSTR];    //  9216 B
    __shared__ float sb1[64], sb3[64];
    const int tid = threadIdx.x;
    const int w = tid >> 5, lane = tid & 31;
    const int nodeBase = blockIdx.x * 256;

    if (tid < 64) { sb1[tid] = b1[tid]; sb3[tid] = b3[tid]; }

    // A tile: 256 rows x 64 halves (fp32 h -> fp16), padded rows
    const float4* h4 = (const float4*)h;
    #pragma unroll
    for (int i = 0; i < 8; i++) {
        int chunk = i * 512 + tid;          // 0..4095
        int r = chunk >> 4, ci = chunk & 15;
        int gn = nodeBase + r;
        float4 v = make_float4(0.f, 0.f, 0.f, 0.f);
        if (gn < NN) v = h4[(size_t)gn * 16 + ci];
        __half2 p0 = __floats2half2_rn(v.x, v.y);
        __half2 p1 = __floats2half2_rn(v.z, v.w);
        *(uint2*)(sA + r * GSTR + ci * 8) =
            make_uint2(*(uint32_t*)&p0, *(uint32_t*)&p1);
    }
    __syncthreads();

    // A fragments: 4 k-steps, ldmatrix.x4 each (rows w*16..+15, k 16 per step)
    uint32_t af[16];
    {
        uint32_t abase = smem_u32(sA);
        int arow = w * 16 + (lane & 15);
        int acol = (lane >> 4) * 8;         // halves
        #pragma unroll
        for (int k = 0; k < 4; k++) {
            uint32_t addr = abase + arow * GSTR + (k * 16 + acol) * 2;
            asm volatile("ldmatrix.sync.aligned.m8n8.x4.shared.b16 {%0,%1,%2,%3}, [%4];"
                         : "=r"(af[k*4+0]), "=r"(af[k*4+1]),
                           "=r"(af[k*4+2]), "=r"(af[k*4+3])
                         : "r"(addr));
        }
    }

    const int g = lane >> 2, tig = lane & 3;
    const int row0 = nodeBase + w * 16 + g;
    const int row1 = row0 + 8;
    float dw0 = 0.f, dw1 = 0.f;
    if (row0 < NN) dw0 = degw[row0];
    if (row1 < NN) dw1 = degw[row1];

    float bacc[32];
    const uint32_t bbase = smem_u32(sB);
    const int brow_off = (lane & 7) * GSTR;
    const int bcol_off = ((lane >> 3) & 1) * 16;   // bytes (8 halves)

    #pragma unroll 1
    for (int m = 0; m < 3; m++) {
        __syncthreads();
        {   // load W_m^T tile: 64 rows x 64 halves
            uint4 v = ((const uint4*)(wt + m * 4096))[tid];
            int r = tid >> 3, ci = tid & 7;
            *(uint4*)(sB + r * GSTR + ci * 16) = v;
        }
        __syncthreads();

        #pragma unroll
        for (int f = 0; f < 8; f++) {
            float c0 = 0.f, c1 = 0.f, c2 = 0.f, c3 = 0.f;
            #pragma unroll
            for (int k = 0; k < 4; k++) {
                uint32_t baddr = bbase + f * 8 * GSTR + brow_off + k * 32 + bcol_off;
                uint32_t b0r, b1r;
                asm volatile("ldmatrix.sync.aligned.m8n8.x2.shared.b16 {%0,%1}, [%2];"
                             : "=r"(b0r), "=r"(b1r) : "r"(baddr));
                asm volatile("mma.sync.aligned.m16n8k16.row.col.f32.f16.f16.f32 "
                             "{%0,%1,%2,%3}, {%4,%5,%6,%7}, {%8,%9}, {%0,%1,%2,%3};"
                             : "+f"(c0), "+f"(c1), "+f"(c2), "+f"(c3)
                             : "r"(af[k*4+0]), "r"(af[k*4+1]),
                               "r"(af[k*4+2]), "r"(af[k*4+3]),
                               "r"(b0r), "r"(b1r));
            }
            const int col = f * 8 + 2 * tig;
            if (m == 0) {
                if (row0 < NN)
                    *(__half2*)(a_out + (size_t)row0 * 64 + col) =
                        __floats2half2_rn(c0 + sb1[col], c1 + sb1[col + 1]);
                if (row1 < NN)
                    *(__half2*)(a_out + (size_t)row1 * 64 + col) =
                        __floats2half2_rn(c2 + sb1[col], c3 + sb1[col + 1]);
            } else if (m == 1) {
                bacc[f*4+0] = c0; bacc[f*4+1] = c1;
                bacc[f*4+2] = c2; bacc[f*4+3] = c3;
            } else {
                if (row0 < NN) {
                    float2 o = make_float2(c0 + sb3[col]     - dw0 * bacc[f*4+0],
                                           c1 + sb3[col + 1] - dw0 * bacc[f*4+1]);
                    __stcs((float2*)(z_out + (size_t)row0 * 64 + col), o);
                }
                if (row1 < NN) {
                    float2 o = make_float2(c2 + sb3[col]     - dw1 * bacc[f*4+2],
                                           c3 + sb3[col + 1] - dw1 * bacc[f*4+3]);
                    __stcs((float2*)(z_out + (size_t)row1 * 64 + col), o);
                }
            }
        }
    }
}

// ---------------- gather: h[n] = relu(z[n] + sum_{e->n} w_e * fp32(a[src_e])) --------
// (R10 form — best known) fp16 `a` rows = 128B = one cache line. 8 lanes/node.
__global__ __launch_bounds__(256) void gather_kernel(
                              const int* __restrict__ rowstart,
                              const int* __restrict__ cnt,
                              const int2* __restrict__ epack,
                              const __half* __restrict__ a,
                              const float* __restrict__ z,
                              float* __restrict__ h,
                              const int* __restrict__ batch,
                              float* __restrict__ psum,
                              float* __restrict__ pcnt,
                              int do_pool) {
    int t = blockIdx.x * blockDim.x + threadIdx.x;
    int n = t >> 3;
    if (n >= NN) return;
    int lane = t & 7;
    int s = __ldg(rowstart + n);
    int c = __ldg(cnt + n);
    const uint4* a4 = (const uint4*)a;

    const float4* zp4 = (const float4*)z + (size_t)n * 16 + lane * 2;
    float4 acc0 = __ldcs(zp4);
    float4 acc1 = __ldcs(zp4 + 1);

    #define ACC_EDGE(V, W) do {                                              \
        const __half2* hv_ = (const __half2*)&(V);                           \
        float2 f0_ = __half22float2(hv_[0]);                                 \
        float2 f1_ = __half22float2(hv_[1]);                                 \
        float2 f2_ = __half22float2(hv_[2]);                                 \
        float2 f3_ = __half22float2(hv_[3]);                                 \
        acc0.x = fmaf((W), f0_.x, acc0.x); acc0.y = fmaf((W), f0_.y, acc0.y);\
        acc0.z = fmaf((W), f1_.x, acc0.z); acc0.w = fmaf((W), f1_.y, acc0.w);\
        acc1.x = fmaf((W), f2_.x, acc1.x); acc1.y = fmaf((W), f2_.y, acc1.y);\
        acc1.z = fmaf((W), f3_.x, acc1.z); acc1.w = fmaf((W), f3_.y, acc1.w);\
    } while (0)

    int j = 0;
    for (; j + 4 <= c; j += 4) {
        int2 p0 = __ldg(epack + s + j);
        int2 p1 = __ldg(epack + s + j + 1);
        int2 p2 = __ldg(epack + s + j + 2);
        int2 p3 = __ldg(epack + s + j + 3);
        uint4 v0 = __ldg(a4 + (size_t)p0.x * 8 + lane);
        uint4 v1 = __ldg(a4 + (size_t)p1.x * 8 + lane);
        uint4 v2 = __ldg(a4 + (size_t)p2.x * 8 + lane);
        uint4 v3 = __ldg(a4 + (size_t)p3.x * 8 + lane);
        float w0 = __int_as_float(p0.y);
        float w1 = __int_as_float(p1.y);
        float w2 = __int_as_float(p2.y);
        float w3 = __int_as_float(p3.y);
        ACC_EDGE(v0, w0);
        ACC_EDGE(v1, w1);
        ACC_EDGE(v2, w2);
        ACC_EDGE(v3, w3);
    }
    for (; j < c; j++) {
        int2 p0 = __ldg(epack + s + j);
        float w0 = __int_as_float(p0.y);
        uint4 v0 = __ldg(a4 + (size_t)p0.x * 8 + lane);
        ACC_EDGE(v0, w0);
    }
    #undef ACC_EDGE

    acc0.x = fmaxf(acc0.x, 0.f); acc0.y = fmaxf(acc0.y, 0.f);
    acc0.z = fmaxf(acc0.z, 0.f); acc0.w = fmaxf(acc0.w, 0.f);
    acc1.x = fmaxf(acc1.x, 0.f); acc1.y = fmaxf(acc1.y, 0.f);
    acc1.z = fmaxf(acc1.z, 0.f); acc1.w = fmaxf(acc1.w, 0.f);
    float4* hp4 = (float4*)h + (size_t)n * 16 + lane * 2;
    hp4[0] = acc0;
    hp4[1] = acc1;

    if (do_pool) {
        int g = __ldg(batch + n);
        float* p = psum + (size_t)g * 64 + lane * 8;
        asm volatile("red.global.add.v4.f32 [%0], {%1, %2, %3, %4};"
                     :: "l"(p), "f"(acc0.x), "f"(acc0.y), "f"(acc0.z), "f"(acc0.w) : "memory");
        asm volatile("red.global.add.v4.f32 [%0], {%1, %2, %3, %4};"
                     :: "l"(p + 4), "f"(acc1.x), "f"(acc1.y), "f"(acc1.z), "f"(acc1.w) : "memory");
        if (lane == 0)
            asm volatile("red.global.add.f32 [%0], %1;" :: "l"(pcnt + g), "f"(1.0f) : "memory");
    }
}

// ---------------- final MLP head ----------------
__global__ void mlp_kernel(const float* __restrict__ psum,
                           const float* __restrict__ pcnt,
                           const float* __restrict__ Wl1, const float* __restrict__ bl1,
                           const float* __restrict__ Wl2, const float* __restrict__ bl2,
                           float* __restrict__ out) {
    __shared__ float sW1[64 * 32];
    __shared__ float sW2[32 * 3];
    __shared__ float sb1[32];
    __shared__ float sb2[3];
    int tid = threadIdx.x;
    for (int i = tid; i < 64 * 32; i += blockDim.x) sW1[i] = Wl1[i];
    for (int i = tid; i < 32 * 3; i += blockDim.x) sW2[i] = Wl2[i];
    if (tid < 32) sb1[tid] = bl1[tid];
    if (tid < 3) sb2[tid] = bl2[tid];
    __syncthreads();

    int g = blockIdx.x * blockDim.x + tid;
    if (g >= GG) return;
    float inv = 1.0f / fmaxf(pcnt[g], 1.0f);
    float hid[32];
    #pragma unroll
    for (int j = 0; j < 32; j++) hid[j] = sb1[j];
    #pragma unroll 8
    for (int k = 0; k < 64; k++) {
        float xv = psum[(size_t)g * 64 + k] * inv;
        #pragma unroll
        for (int j = 0; j < 32; j++) hid[j] += xv * sW1[k * 32 + j];
    }
    #pragma unroll
    for (int j = 0; j < 32; j++) hid[j] = fmaxf(hid[j], 0.f);
    #pragma unroll
    for (int c = 0; c < 3; c++) {
        float o = sb2[c];
        #pragma unroll
        for (int j = 0; j < 32; j++) o += hid[j] * sW2[j * 3 + c];
        out[g * 3 + c] = o;
    }
}

// ---------------- launch ----------------
extern "C" void kernel_launch(void* const* d_in, const int* in_sizes, int n_in,
                              void* d_out, int out_size) {
    const float* x        = (const float*)d_in[0];
    const int*   ei32     = (const int*)d_in[1];
    const float* ea       = (const float*)d_in[2];
    const int*   b32      = (const int*)d_in[3];
    const float* Wemb     = (const float*)d_in[4];
    const float* bemb     = (const float*)d_in[5];
    const float* W1       = (const float*)d_in[6];
    const float* b1       = (const float*)d_in[7];
    const float* W2       = (const float*)d_in[8];
    const float* W3       = (const float*)d_in[9];
    const float* b3       = (const float*)d_in[10];
    const float* Wl1      = (const float*)d_in[11];
    const float* bl1      = (const float*)d_in[12];
    const float* Wl2      = (const float*)d_in[13];
    const float* bl2      = (const float*)d_in[14];
    float* out = (float*)d_out;

    float *hp, *zp, *dwp, *psp, *pcp;
    __half *ap, *wtp;
    int *cntp, *rsp, *curp, *bsp, *bop, *bp, *efp, *bfp;
    int2* epp;
    cudaGetSymbolAddress((void**)&hp, g_h);
    cudaGetSymbolAddress((void**)&ap, g_a);
    cudaGetSymbolAddress((void**)&zp, g_z);
    cudaGetSymbolAddress((void**)&dwp, g_degw);
    cudaGetSymbolAddress((void**)&psp, g_psum);
    cudaGetSymbolAddress((void**)&pcp, g_pcnt);
    cudaGetSymbolAddress((void**)&cntp, g_cnt);
    cudaGetSymbolAddress((void**)&rsp, g_rowstart);
    cudaGetSymbolAddress((void**)&curp, g_cursor);
    cudaGetSymbolAddress((void**)&bsp, g_bsum);
    cudaGetSymbolAddress((void**)&bop, g_boff);
    cudaGetSymbolAddress((void**)&epp, g_epack);
    cudaGetSymbolAddress((void**)&bp, g_batch);
    cudaGetSymbolAddress((void**)&wtp, g_wt);
    cudaGetSymbolAddress((void**)&efp, g_eflag);
    cudaGetSymbolAddress((void**)&bfp, g_bflag);

    cudaMemsetAsync(cntp, 0, NN * sizeof(int));
    cudaMemsetAsync(psp, 0, GG * DD * sizeof(float));
    cudaMemsetAsync(pcp, 0, GG * sizeof(float));

    const int scanBlocks = (NN + 255) / 256;   // 391

    detect_kernel<<<1, 256>>>(ei32, b32, efp, bfp);
    cvt_batch_kernel<<<(NN + 255) / 256, 256>>>(b32, bp, bfp);
    hist_kernel<<<(EE + 255) / 256, 256>>>(ei32, cntp, efp);
    scan1_kernel<<<scanBlocks, 256>>>(cntp, rsp, bsp);
    scan2_kernel<<<1, 512>>>(bsp, bop, scanBlocks);
    scan3_kernel<<<scanBlocks, 256>>>(rsp, curp, bop);
    fill_kernel<<<(EE + 255) / 256, 256>>>(ei32, ea, curp, epp, efp);
    degw_kernel<<<(NN + 255) / 256, 256>>>(rsp, cntp, epp, dwp);
    prep_wt_kernel<<<(9 * 4096 + 255) / 256, 256>>>(W1, W2, W3, wtp);

    embed_kernel<<<(NN * 16 + 255) / 256, 256>>>(x, Wemb, bemb, hp);

    const int gemmBlocks = (NN + 255) / 256;   // 391
    const int gatherBlocks = (NN * 8 + 255) / 256;

    for (int l = 0; l < 3; l++) {
        gemm3_mma_kernel<<<gemmBlocks, 512>>>(hp, wtp + (size_t)l * 12288,
                                              b1 + (size_t)l * DD,
                                              b3 + (size_t)l * DD,
                                              dwp, ap, zp);
        gather_kernel<<<gatherBlocks, 256>>>(rsp, cntp, epp, ap, zp, hp,
                                             bp, psp, pcp, (l == 2) ? 1 : 0);
    }

    mlp_kernel<<<2, 256>>>(psp, pcp, Wl1, bl1, Wl2, bl2, out);
}